// round 1
// baseline (speedup 1.0000x reference)
#include <cuda_runtime.h>
#include <cuda_bf16.h>
#include <cstdint>

using bf16 = __nv_bfloat16;

// Problem constants (fixed shapes from setup_inputs):
//   x [4,2048,4096] -> X [8192,4096]; W [4096,4096]; b [4096]
//   A_u [8,4096]; B_u [4096,8]; A0 [56,2048]; B0 [2048,56]
// out [8192,4096] fp32
static const int MTOT = 8192;
static const int NTOT = 4096;
static const int KTOT = 4096;

// Scratch (allocation-free rule: __device__ globals)
__device__ bf16 g_Xh[(size_t)MTOT * KTOT];
__device__ bf16 g_Xl[(size_t)MTOT * KTOT];
__device__ bf16 g_Wh[(size_t)NTOT * KTOT];
__device__ bf16 g_Wl[(size_t)NTOT * KTOT];

// ---------------------------------------------------------------------------
// Kernel 1: split X into bf16 hi/lo
// ---------------------------------------------------------------------------
__global__ void split_x_kernel(const float4* __restrict__ x, int n4) {
    int i = blockIdx.x * blockDim.x + threadIdx.x;
    if (i >= n4) return;
    float4 v = x[i];
    float a[4] = {v.x, v.y, v.z, v.w};
    ushort4 hh, ll;
    unsigned short* hp = &hh.x;
    unsigned short* lp = &ll.x;
#pragma unroll
    for (int j = 0; j < 4; j++) {
        bf16 h = __float2bfloat16(a[j]);
        float r = a[j] - __bfloat162float(h);
        bf16 l = __float2bfloat16(r);
        hp[j] = __bfloat16_as_ushort(h);
        lp[j] = __bfloat16_as_ushort(l);
    }
    reinterpret_cast<ushort4*>(g_Xh)[i] = hh;
    reinterpret_cast<ushort4*>(g_Xl)[i] = ll;
}

// ---------------------------------------------------------------------------
// Kernel 2: W_eff = W + B_u A_u + B_s A_s, split into bf16 hi/lo.
//   delta_s[n,k] = sum_t B0[n%2048, t] * A0[(t + n/2048 - k/2048) mod 56, k%2048]
// Block: 128 threads = one k per thread (k-tile 128), n-tile 32.
// ---------------------------------------------------------------------------
__global__ void build_w_kernel(const float* __restrict__ W,
                               const float* __restrict__ A_u,
                               const float* __restrict__ B_u,
                               const float* __restrict__ A0,
                               const float* __restrict__ B0) {
    __shared__ float sAu[8][128];
    __shared__ float sA0[56][128];
    __shared__ float sBu[32][8];
    __shared__ float sB0[32][56];

    int tid = threadIdx.x;                 // 0..127
    int k = blockIdx.x * 128 + tid;
    int i = k >> 11;                       // k / 2048 (constant per block)
    int kk = k & 2047;
    int nbase = blockIdx.y * 32;
    int j = nbase >> 11;                   // n / 2048 (constant per block)
    int nb2 = nbase & 2047;

#pragma unroll
    for (int u = 0; u < 8; u++) sAu[u][tid] = A_u[u * 4096 + k];
#pragma unroll
    for (int r = 0; r < 56; r++) sA0[r][tid] = A0[r * 2048 + kk];
    for (int idx = tid; idx < 32 * 8; idx += 128) {
        int ln = idx >> 3, u = idx & 7;
        sBu[ln][u] = B_u[(nbase + ln) * 8 + u];
    }
    for (int idx = tid; idx < 32 * 56; idx += 128) {
        int ln = idx / 56, t = idx % 56;
        sB0[ln][t] = B0[(nb2 + ln) * 56 + t];
    }
    __syncthreads();

    int d = j - i;  // -1, 0, or 1
    for (int ln = 0; ln < 32; ln++) {
        int n = nbase + ln;
        float acc = W[(size_t)n * 4096 + k];
#pragma unroll
        for (int u = 0; u < 8; u++) acc += sBu[ln][u] * sAu[u][tid];
#pragma unroll
        for (int t = 0; t < 56; t++) {
            int rr = t + d;
            rr = (rr >= 56) ? rr - 56 : (rr < 0 ? rr + 56 : rr);
            acc += sB0[ln][t] * sA0[rr][tid];
        }
        bf16 h = __float2bfloat16(acc);
        float rres = acc - __bfloat162float(h);
        g_Wh[(size_t)n * 4096 + k] = h;
        g_Wl[(size_t)n * 4096 + k] = __float2bfloat16(rres);
    }
}

// ---------------------------------------------------------------------------
// Kernel 3: GEMM  out = Xh*Wh^T + Xh*Wl^T + Xl*Wh^T + b
// CTA tile 128x128xBK64, 256 threads (8 warps as 2x4), 3-stage cp.async.
// smem per stage: Ah/Al/Bh/Bl 128x64 bf16 each (16KB) = 64KB; 3 stages = 192KB.
// XOR swizzle on 16B chunks: chunk' = chunk ^ (row & 7)  (128B rows).
// ---------------------------------------------------------------------------
#define SSTAGE 65536

__device__ __forceinline__ void cp16(uint32_t dst, const void* src) {
    asm volatile("cp.async.cg.shared.global [%0], [%1], 16;" :: "r"(dst), "l"(src));
}
__device__ __forceinline__ void ldsm4(uint32_t& r0, uint32_t& r1, uint32_t& r2,
                                      uint32_t& r3, uint32_t addr) {
    asm volatile("ldmatrix.sync.aligned.m8n8.x4.shared.b16 {%0,%1,%2,%3}, [%4];"
                 : "=r"(r0), "=r"(r1), "=r"(r2), "=r"(r3) : "r"(addr));
}
__device__ __forceinline__ void mma16816(float* c, const uint32_t* a,
                                         uint32_t b0, uint32_t b1) {
    asm volatile(
        "mma.sync.aligned.m16n8k16.row.col.f32.bf16.bf16.f32 "
        "{%0,%1,%2,%3},{%4,%5,%6,%7},{%8,%9},{%0,%1,%2,%3};"
        : "+f"(c[0]), "+f"(c[1]), "+f"(c[2]), "+f"(c[3])
        : "r"(a[0]), "r"(a[1]), "r"(a[2]), "r"(a[3]), "r"(b0), "r"(b1));
}

__global__ void __launch_bounds__(256, 1)
gemm_kernel(const float* __restrict__ bias, float* __restrict__ out) {
    extern __shared__ char smem[];
    uint32_t sbase = (uint32_t)__cvta_generic_to_shared(smem);
    int tid = threadIdx.x;
    int lane = tid & 31, warp = tid >> 5;
    int wm = warp >> 2;   // 0..1 : 64 rows each
    int wn = warp & 3;    // 0..3 : 32 cols each
    int bm = blockIdx.y, bn = blockIdx.x;

    const bf16* gA0 = g_Xh + (size_t)bm * 128 * 4096;
    const bf16* gA1 = g_Xl + (size_t)bm * 128 * 4096;
    const bf16* gB0 = g_Wh + (size_t)bn * 128 * 4096;
    const bf16* gB1 = g_Wl + (size_t)bn * 128 * 4096;

    auto load_stage = [&](int s, int kt) {
        uint32_t st = sbase + s * SSTAGE;
#pragma unroll
        for (int arr = 0; arr < 4; arr++) {
            const bf16* g = (arr == 0) ? gA0 : (arr == 1) ? gA1 : (arr == 2) ? gB0 : gB1;
            uint32_t ab = st + arr * 16384;
#pragma unroll
            for (int i2 = 0; i2 < 4; i2++) {
                int idx = tid + i2 * 256;
                int r = idx >> 3, c = idx & 7;
                uint32_t dst = ab + r * 128 + ((c ^ (r & 7)) << 4);
                cp16(dst, g + (size_t)r * 4096 + kt * 64 + c * 8);
            }
        }
    };

    float acc[4][4][4];
#pragma unroll
    for (int a = 0; a < 4; a++)
#pragma unroll
        for (int b = 0; b < 4; b++)
#pragma unroll
            for (int c = 0; c < 4; c++) acc[a][b][c] = 0.0f;

    load_stage(0, 0);
    asm volatile("cp.async.commit_group;");
    load_stage(1, 1);
    asm volatile("cp.async.commit_group;");

    const int KT = KTOT / 64;  // 64
    int cs = 0, ls = 2;
    for (int kt = 0; kt < KT; kt++) {
        asm volatile("cp.async.wait_group 1;");
        __syncthreads();
        if (kt + 2 < KT) load_stage(ls, kt + 2);
        asm volatile("cp.async.commit_group;");

        uint32_t st = sbase + cs * SSTAGE;
        int arow = wm * 64 + (lane & 15);
        int nrow = wn * 32 + (lane & 7) + ((lane >> 4) << 3);
#pragma unroll
        for (int ks = 0; ks < 4; ks++) {
            uint32_t ah[4][4], al[4][4], bh[2][4], bl[2][4];
            int ach = ks * 2 + (lane >> 4);
            int bch = ks * 2 + ((lane >> 3) & 1);
#pragma unroll
            for (int mt = 0; mt < 4; mt++) {
                int row = arow + mt * 16;
                uint32_t off = row * 128 + ((ach ^ (row & 7)) << 4);
                ldsm4(ah[mt][0], ah[mt][1], ah[mt][2], ah[mt][3], st + off);
                ldsm4(al[mt][0], al[mt][1], al[mt][2], al[mt][3], st + 16384 + off);
            }
#pragma unroll
            for (int q = 0; q < 2; q++) {
                int row = nrow + q * 16;
                uint32_t off = row * 128 + ((bch ^ (row & 7)) << 4);
                ldsm4(bh[q][0], bh[q][1], bh[q][2], bh[q][3], st + 32768 + off);
                ldsm4(bl[q][0], bl[q][1], bl[q][2], bl[q][3], st + 49152 + off);
            }
#pragma unroll
            for (int mt = 0; mt < 4; mt++) {
#pragma unroll
                for (int nt = 0; nt < 4; nt++) {
                    int q = nt >> 1, o = (nt & 1) * 2;
                    mma16816(acc[mt][nt], ah[mt], bh[q][o], bh[q][o + 1]);
                    mma16816(acc[mt][nt], ah[mt], bl[q][o], bl[q][o + 1]);
                    mma16816(acc[mt][nt], al[mt], bh[q][o], bh[q][o + 1]);
                }
            }
        }
        cs = (cs == 2) ? 0 : cs + 1;
        ls = (ls == 2) ? 0 : ls + 1;
    }

    // Epilogue: add bias, write fp32
    const float* bptr = bias + bn * 128 + wn * 32;
    size_t outbase = (size_t)(bm * 128 + wm * 64) * 4096 + bn * 128 + wn * 32;
    int gid = lane >> 2, tig = lane & 3;
#pragma unroll
    for (int nt = 0; nt < 4; nt++) {
        int c = nt * 8 + tig * 2;
        float b0 = bptr[c], b1 = bptr[c + 1];
#pragma unroll
        for (int mt = 0; mt < 4; mt++) {
            int r = mt * 16 + gid;
            float2 v0 = make_float2(acc[mt][nt][0] + b0, acc[mt][nt][1] + b1);
            float2 v1 = make_float2(acc[mt][nt][2] + b0, acc[mt][nt][3] + b1);
            *reinterpret_cast<float2*>(out + outbase + (size_t)r * 4096 + c) = v0;
            *reinterpret_cast<float2*>(out + outbase + (size_t)(r + 8) * 4096 + c) = v1;
        }
    }
}

// ---------------------------------------------------------------------------
extern "C" void kernel_launch(void* const* d_in, const int* in_sizes, int n_in,
                              void* d_out, int out_size) {
    const float* x  = (const float*)d_in[0];
    const float* W  = (const float*)d_in[1];
    const float* b  = (const float*)d_in[2];
    const float* Au = (const float*)d_in[3];
    const float* Bu = (const float*)d_in[4];
    const float* A0 = (const float*)d_in[5];
    const float* B0 = (const float*)d_in[6];
    float* out = (float*)d_out;

    // 1) split X -> bf16 hi/lo
    int n4 = (MTOT * KTOT) / 4;
    split_x_kernel<<<(n4 + 255) / 256, 256>>>((const float4*)x, n4);

    // 2) build W_eff and split -> bf16 hi/lo
    build_w_kernel<<<dim3(KTOT / 128, NTOT / 32), 128>>>(W, Au, Bu, A0, B0);

    // 3) main GEMM (+bias)
    cudaFuncSetAttribute(gemm_kernel,
                         cudaFuncAttributeMaxDynamicSharedMemorySize, 3 * SSTAGE);
    gemm_kernel<<<dim3(NTOT / 128, MTOT / 128), 256, 3 * SSTAGE>>>(b, out);
}

// round 3
// speedup vs baseline: 2.2308x; 2.2308x over previous
#include <cuda_runtime.h>
#include <cuda_fp16.h>
#include <cstdint>

// Shapes: X [8192,4096] fp32, W [4096,4096], b[4096], out [8192,4096] fp32.
static const int MTOT = 8192;
static const int NTOT = 4096;
static const int KTOT = 4096;

// GEMM tiling
#define BM 128
#define BN 256
#define BK 64
#define SSTAGE 65536        // Xh 16K + Xl 16K + Wh 32K
#define NCHUNK (KTOT / BK)  // 64

// Scratch (__device__ globals; allocation-free rule)
__device__ __align__(1024) __half g_Xh[(size_t)MTOT * KTOT];
__device__ __align__(1024) __half g_Xl[(size_t)MTOT * KTOT];
__device__ __align__(1024) __half g_Wh[(size_t)NTOT * KTOT];

// ---------------------------------------------------------------------------
// Kernel 1: split X into fp16 hi/lo
// ---------------------------------------------------------------------------
__global__ void split_x_kernel(const float4* __restrict__ x, int n4) {
    int i = blockIdx.x * blockDim.x + threadIdx.x;
    if (i >= n4) return;
    float4 v = x[i];
    float a[4] = {v.x, v.y, v.z, v.w};
    ushort4 hh, ll;
    unsigned short* hp = &hh.x;
    unsigned short* lp = &ll.x;
#pragma unroll
    for (int j = 0; j < 4; j++) {
        __half h = __float2half_rn(a[j]);
        float r = a[j] - __half2float(h);
        hp[j] = __half_as_ushort(h);
        lp[j] = __half_as_ushort(__float2half_rn(r));
    }
    reinterpret_cast<ushort4*>(g_Xh)[i] = hh;
    reinterpret_cast<ushort4*>(g_Xl)[i] = ll;
}

// ---------------------------------------------------------------------------
// Kernel 2: W_eff = W + B_u A_u + B_s A_s  ->  fp16
//   delta_s[n,k] = sum_t B0[n%2048, t] * A0[(t + n/2048 - k/2048) mod 56, k%2048]
// ---------------------------------------------------------------------------
__global__ void build_w_kernel(const float* __restrict__ W,
                               const float* __restrict__ A_u,
                               const float* __restrict__ B_u,
                               const float* __restrict__ A0,
                               const float* __restrict__ B0) {
    __shared__ float sAu[8][128];
    __shared__ float sA0[56][128];
    __shared__ float sBu[32][8];
    __shared__ float sB0[32][56];

    int tid = threadIdx.x;                 // 0..127
    int k = blockIdx.x * 128 + tid;
    int i = k >> 11;
    int kk = k & 2047;
    int nbase = blockIdx.y * 32;
    int j = nbase >> 11;
    int nb2 = nbase & 2047;

#pragma unroll
    for (int u = 0; u < 8; u++) sAu[u][tid] = A_u[u * 4096 + k];
#pragma unroll
    for (int r = 0; r < 56; r++) sA0[r][tid] = A0[r * 2048 + kk];
    for (int idx = tid; idx < 32 * 8; idx += 128) {
        int ln = idx >> 3, u = idx & 7;
        sBu[ln][u] = B_u[(nbase + ln) * 8 + u];
    }
    for (int idx = tid; idx < 32 * 56; idx += 128) {
        int ln = idx / 56, t = idx % 56;
        sB0[ln][t] = B0[(nb2 + ln) * 56 + t];
    }
    __syncthreads();

    int d = j - i;  // -1, 0, or 1
    for (int ln = 0; ln < 32; ln++) {
        int n = nbase + ln;
        float acc = W[(size_t)n * 4096 + k];
#pragma unroll
        for (int u = 0; u < 8; u++) acc += sBu[ln][u] * sAu[u][tid];
#pragma unroll
        for (int t = 0; t < 56; t++) {
            int rr = t + d;
            rr = (rr >= 56) ? rr - 56 : (rr < 0 ? rr + 56 : rr);
            acc += sB0[ln][t] * sA0[rr][tid];
        }
        g_Wh[(size_t)n * 4096 + k] = __float2half_rn(acc);
    }
}

// ---------------------------------------------------------------------------
// Kernel 3: GEMM  out = (Xh + Xl) * Wh^T + b   (fp16 inputs, fp32 accum)
// CTA tile 128x256xBK64, 512 threads (16 warps, 4x4), warp tile 32x64,
// 3-stage cp.async pipeline, XOR-swizzled smem.
// ---------------------------------------------------------------------------
__device__ __forceinline__ void cp16(uint32_t dst, const void* src) {
    asm volatile("cp.async.cg.shared.global [%0], [%1], 16;" :: "r"(dst), "l"(src));
}
__device__ __forceinline__ void ldsm4(uint32_t& r0, uint32_t& r1, uint32_t& r2,
                                      uint32_t& r3, uint32_t addr) {
    asm volatile("ldmatrix.sync.aligned.m8n8.x4.shared.b16 {%0,%1,%2,%3}, [%4];"
                 : "=r"(r0), "=r"(r1), "=r"(r2), "=r"(r3) : "r"(addr));
}
__device__ __forceinline__ void mma16816(float* c, const uint32_t* a,
                                         uint32_t b0, uint32_t b1) {
    asm volatile(
        "mma.sync.aligned.m16n8k16.row.col.f32.f16.f16.f32 "
        "{%0,%1,%2,%3},{%4,%5,%6,%7},{%8,%9},{%0,%1,%2,%3};"
        : "+f"(c[0]), "+f"(c[1]), "+f"(c[2]), "+f"(c[3])
        : "r"(a[0]), "r"(a[1]), "r"(a[2]), "r"(a[3]), "r"(b0), "r"(b1));
}

__global__ void __launch_bounds__(512, 1)
gemm_kernel(const float* __restrict__ bias, float* __restrict__ out) {
    extern __shared__ char smem[];
    uint32_t sbase = (uint32_t)__cvta_generic_to_shared(smem);
    int tid = threadIdx.x;
    int lane = tid & 31, warp = tid >> 5;
    int wm = warp >> 2;   // 0..3 : 32 rows each
    int wn = warp & 3;    // 0..3 : 64 cols each
    int bm = blockIdx.y, bn = blockIdx.x;

    const __half* gXh = g_Xh + (size_t)bm * BM * 4096;
    const __half* gXl = g_Xl + (size_t)bm * BM * 4096;
    const __half* gWh = g_Wh + (size_t)bn * BN * 4096;

    auto load_stage = [&](int s, int kt) {
        uint32_t st = sbase + s * SSTAGE;
        // Xh: 128 rows x 8 chunks = 1024 ops (2 per thread)
#pragma unroll
        for (int i2 = 0; i2 < 2; i2++) {
            int idx = tid + i2 * 512;
            int r = idx >> 3, c = idx & 7;
            uint32_t dst = st + r * 128 + ((c ^ (r & 7)) << 4);
            cp16(dst, gXh + (size_t)r * 4096 + kt * 64 + c * 8);
        }
#pragma unroll
        for (int i2 = 0; i2 < 2; i2++) {
            int idx = tid + i2 * 512;
            int r = idx >> 3, c = idx & 7;
            uint32_t dst = st + 16384 + r * 128 + ((c ^ (r & 7)) << 4);
            cp16(dst, gXl + (size_t)r * 4096 + kt * 64 + c * 8);
        }
        // Wh: 256 rows x 8 chunks = 2048 ops (4 per thread)
#pragma unroll
        for (int i2 = 0; i2 < 4; i2++) {
            int idx = tid + i2 * 512;
            int r = idx >> 3, c = idx & 7;
            uint32_t dst = st + 32768 + r * 128 + ((c ^ (r & 7)) << 4);
            cp16(dst, gWh + (size_t)r * 4096 + kt * 64 + c * 8);
        }
    };

    float acc[2][8][4];
#pragma unroll
    for (int a = 0; a < 2; a++)
#pragma unroll
        for (int b = 0; b < 8; b++)
#pragma unroll
            for (int c = 0; c < 4; c++) acc[a][b][c] = 0.0f;

    load_stage(0, 0);
    asm volatile("cp.async.commit_group;");
    load_stage(1, 1);
    asm volatile("cp.async.commit_group;");

    int arow = wm * 32 + (lane & 15);
    int nrow0 = wn * 64 + (lane & 7) + ((lane >> 4) << 3);

    int cs = 0, ls = 2;
    for (int kt = 0; kt < NCHUNK; kt++) {
        asm volatile("cp.async.wait_group 1;");
        __syncthreads();
        if (kt + 2 < NCHUNK) load_stage(ls, kt + 2);
        asm volatile("cp.async.commit_group;");

        uint32_t st = sbase + cs * SSTAGE;
#pragma unroll
        for (int ks = 0; ks < 4; ks++) {
            uint32_t ah[2][4], al[2][4], bh[4][4];
            int ach = ks * 2 + (lane >> 4);
            int bch = ks * 2 + ((lane >> 3) & 1);
#pragma unroll
            for (int mt = 0; mt < 2; mt++) {
                int row = arow + mt * 16;
                uint32_t off = row * 128 + ((ach ^ (row & 7)) << 4);
                ldsm4(ah[mt][0], ah[mt][1], ah[mt][2], ah[mt][3], st + off);
                ldsm4(al[mt][0], al[mt][1], al[mt][2], al[mt][3], st + 16384 + off);
            }
#pragma unroll
            for (int q = 0; q < 4; q++) {
                int row = nrow0 + q * 16;
                uint32_t off = row * 128 + ((bch ^ (row & 7)) << 4);
                ldsm4(bh[q][0], bh[q][1], bh[q][2], bh[q][3], st + 32768 + off);
            }
#pragma unroll
            for (int mt = 0; mt < 2; mt++) {
#pragma unroll
                for (int nt = 0; nt < 8; nt++) {
                    int q = nt >> 1, o = (nt & 1) * 2;
                    mma16816(acc[mt][nt], ah[mt], bh[q][o], bh[q][o + 1]);
                    mma16816(acc[mt][nt], al[mt], bh[q][o], bh[q][o + 1]);
                }
            }
        }
        cs = (cs == 2) ? 0 : cs + 1;
        ls = (ls == 2) ? 0 : ls + 1;
    }

    // Epilogue: add bias, write fp32 directly
    const float* bptr = bias + bn * BN + wn * 64;
    size_t outbase = (size_t)(bm * BM + wm * 32) * 4096 + bn * BN + wn * 64;
    int gid = lane >> 2, tig = lane & 3;
#pragma unroll
    for (int nt = 0; nt < 8; nt++) {
        int c = nt * 8 + tig * 2;
        float b0 = bptr[c], b1 = bptr[c + 1];
#pragma unroll
        for (int mt = 0; mt < 2; mt++) {
            int r = mt * 16 + gid;
            float2 v0 = make_float2(acc[mt][nt][0] + b0, acc[mt][nt][1] + b1);
            float2 v1 = make_float2(acc[mt][nt][2] + b0, acc[mt][nt][3] + b1);
            *reinterpret_cast<float2*>(out + outbase + (size_t)r * 4096 + c) = v0;
            *reinterpret_cast<float2*>(out + outbase + (size_t)(r + 8) * 4096 + c) = v1;
        }
    }
}

// ---------------------------------------------------------------------------
extern "C" void kernel_launch(void* const* d_in, const int* in_sizes, int n_in,
                              void* d_out, int out_size) {
    const float* x  = (const float*)d_in[0];
    const float* W  = (const float*)d_in[1];
    const float* b  = (const float*)d_in[2];
    const float* Au = (const float*)d_in[3];
    const float* Bu = (const float*)d_in[4];
    const float* A0 = (const float*)d_in[5];
    const float* B0 = (const float*)d_in[6];
    float* out = (float*)d_out;

    int n4 = (MTOT * KTOT) / 4;
    split_x_kernel<<<(n4 + 255) / 256, 256>>>((const float4*)x, n4);
    build_w_kernel<<<dim3(KTOT / 128, NTOT / 32), 128>>>(W, Au, Bu, A0, B0);

    cudaFuncSetAttribute(gemm_kernel,
                         cudaFuncAttributeMaxDynamicSharedMemorySize, 3 * SSTAGE);
    gemm_kernel<<<dim3(NTOT / BN, MTOT / BM), 512, 3 * SSTAGE>>>(b, out);
}

// round 4
// speedup vs baseline: 3.5950x; 1.6115x over previous
#include <cuda_runtime.h>
#include <cuda_fp16.h>
#include <cstdint>

// Shapes: X [8192,4096] fp32, W [4096,4096], b[4096], out [8192,4096] fp32.
static const int MTOT = 8192;
static const int NTOT = 4096;
static const int KTOT = 4096;

// GEMM tiling
#define BM 128
#define BN 256
#define BK 64
#define SSTAGE 49152        // Xh 16K + Wh 32K
#define NSTAGES 4
#define NCHUNK (KTOT / BK)  // 64

// Scratch (__device__ globals; allocation-free rule)
__device__ __align__(1024) __half g_Xh[(size_t)MTOT * KTOT];
__device__ __align__(1024) __half g_Wh[(size_t)NTOT * KTOT];

// ---------------------------------------------------------------------------
// Kernel 1: convert X to fp16
// ---------------------------------------------------------------------------
__global__ void split_x_kernel(const float4* __restrict__ x, int n4) {
    int i = blockIdx.x * blockDim.x + threadIdx.x;
    if (i >= n4) return;
    float4 v = x[i];
    ushort4 hh;
    hh.x = __half_as_ushort(__float2half_rn(v.x));
    hh.y = __half_as_ushort(__float2half_rn(v.y));
    hh.z = __half_as_ushort(__float2half_rn(v.z));
    hh.w = __half_as_ushort(__float2half_rn(v.w));
    reinterpret_cast<ushort4*>(g_Xh)[i] = hh;
}

// ---------------------------------------------------------------------------
// Kernel 2: W_eff = W + B_u A_u + B_s A_s  ->  fp16
//   delta_s[n,k] = sum_t B0[n%2048, t] * A0[(t + n/2048 - k/2048) mod 56, k%2048]
// ---------------------------------------------------------------------------
__global__ void build_w_kernel(const float* __restrict__ W,
                               const float* __restrict__ A_u,
                               const float* __restrict__ B_u,
                               const float* __restrict__ A0,
                               const float* __restrict__ B0) {
    __shared__ float sAu[8][128];
    __shared__ float sA0[56][128];
    __shared__ float sBu[32][8];
    __shared__ float sB0[32][56];

    int tid = threadIdx.x;                 // 0..127
    int k = blockIdx.x * 128 + tid;
    int i = k >> 11;
    int kk = k & 2047;
    int nbase = blockIdx.y * 32;
    int j = nbase >> 11;
    int nb2 = nbase & 2047;

#pragma unroll
    for (int u = 0; u < 8; u++) sAu[u][tid] = A_u[u * 4096 + k];
#pragma unroll
    for (int r = 0; r < 56; r++) sA0[r][tid] = A0[r * 2048 + kk];
    for (int idx = tid; idx < 32 * 8; idx += 128) {
        int ln = idx >> 3, u = idx & 7;
        sBu[ln][u] = B_u[(nbase + ln) * 8 + u];
    }
    for (int idx = tid; idx < 32 * 56; idx += 128) {
        int ln = idx / 56, t = idx % 56;
        sB0[ln][t] = B0[(nb2 + ln) * 56 + t];
    }
    __syncthreads();

    int d = j - i;  // -1, 0, or 1
    for (int ln = 0; ln < 32; ln++) {
        int n = nbase + ln;
        float acc = W[(size_t)n * 4096 + k];
#pragma unroll
        for (int u = 0; u < 8; u++) acc += sBu[ln][u] * sAu[u][tid];
#pragma unroll
        for (int t = 0; t < 56; t++) {
            int rr = t + d;
            rr = (rr >= 56) ? rr - 56 : (rr < 0 ? rr + 56 : rr);
            acc += sB0[ln][t] * sA0[rr][tid];
        }
        g_Wh[(size_t)n * 4096 + k] = __float2half_rn(acc);
    }
}

// ---------------------------------------------------------------------------
// Kernel 3: GEMM  out = Xh * Wh^T + b   (fp16 inputs, fp32 accum)
// CTA tile 128x256xBK64, 512 threads (16 warps, 4x4), warp tile 32x64,
// 4-stage cp.async pipeline, XOR-swizzled smem.
// ---------------------------------------------------------------------------
__device__ __forceinline__ void cp16(uint32_t dst, const void* src) {
    asm volatile("cp.async.cg.shared.global [%0], [%1], 16;" :: "r"(dst), "l"(src));
}
__device__ __forceinline__ void ldsm4(uint32_t& r0, uint32_t& r1, uint32_t& r2,
                                      uint32_t& r3, uint32_t addr) {
    asm volatile("ldmatrix.sync.aligned.m8n8.x4.shared.b16 {%0,%1,%2,%3}, [%4];"
                 : "=r"(r0), "=r"(r1), "=r"(r2), "=r"(r3) : "r"(addr));
}
__device__ __forceinline__ void mma16816(float* c, const uint32_t* a,
                                         uint32_t b0, uint32_t b1) {
    asm volatile(
        "mma.sync.aligned.m16n8k16.row.col.f32.f16.f16.f32 "
        "{%0,%1,%2,%3},{%4,%5,%6,%7},{%8,%9},{%0,%1,%2,%3};"
        : "+f"(c[0]), "+f"(c[1]), "+f"(c[2]), "+f"(c[3])
        : "r"(a[0]), "r"(a[1]), "r"(a[2]), "r"(a[3]), "r"(b0), "r"(b1));
}

__global__ void __launch_bounds__(512, 1)
gemm_kernel(const float* __restrict__ bias, float* __restrict__ out) {
    extern __shared__ char smem[];
    uint32_t sbase = (uint32_t)__cvta_generic_to_shared(smem);
    int tid = threadIdx.x;
    int lane = tid & 31, warp = tid >> 5;
    int wm = warp >> 2;   // 0..3 : 32 rows each
    int wn = warp & 3;    // 0..3 : 64 cols each
    int bm = blockIdx.y, bn = blockIdx.x;

    const __half* gXh = g_Xh + (size_t)bm * BM * 4096;
    const __half* gWh = g_Wh + (size_t)bn * BN * 4096;

    auto load_stage = [&](int s, int kt) {
        uint32_t st = sbase + s * SSTAGE;
        // Xh: 128 rows x 8 chunks = 1024 ops (2 per thread)
#pragma unroll
        for (int i2 = 0; i2 < 2; i2++) {
            int idx = tid + i2 * 512;
            int r = idx >> 3, c = idx & 7;
            uint32_t dst = st + r * 128 + ((c ^ (r & 7)) << 4);
            cp16(dst, gXh + (size_t)r * 4096 + kt * 64 + c * 8);
        }
        // Wh: 256 rows x 8 chunks = 2048 ops (4 per thread)
#pragma unroll
        for (int i2 = 0; i2 < 4; i2++) {
            int idx = tid + i2 * 512;
            int r = idx >> 3, c = idx & 7;
            uint32_t dst = st + 16384 + r * 128 + ((c ^ (r & 7)) << 4);
            cp16(dst, gWh + (size_t)r * 4096 + kt * 64 + c * 8);
        }
    };

    float acc[2][8][4];
#pragma unroll
    for (int a = 0; a < 2; a++)
#pragma unroll
        for (int b = 0; b < 8; b++)
#pragma unroll
            for (int c = 0; c < 4; c++) acc[a][b][c] = 0.0f;

    load_stage(0, 0);
    asm volatile("cp.async.commit_group;");
    load_stage(1, 1);
    asm volatile("cp.async.commit_group;");
    load_stage(2, 2);
    asm volatile("cp.async.commit_group;");

    int arow = wm * 32 + (lane & 15);
    int nrow0 = wn * 64 + (lane & 7) + ((lane >> 4) << 3);

    for (int kt = 0; kt < NCHUNK; kt++) {
        asm volatile("cp.async.wait_group 2;");
        __syncthreads();
        if (kt + 3 < NCHUNK) load_stage((kt + 3) & 3, kt + 3);
        asm volatile("cp.async.commit_group;");

        uint32_t st = sbase + (kt & 3) * SSTAGE;
#pragma unroll
        for (int ks = 0; ks < 4; ks++) {
            uint32_t ah[2][4], bh[4][4];
            int ach = ks * 2 + (lane >> 4);
            int bch = ks * 2 + ((lane >> 3) & 1);
#pragma unroll
            for (int mt = 0; mt < 2; mt++) {
                int row = arow + mt * 16;
                uint32_t off = row * 128 + ((ach ^ (row & 7)) << 4);
                ldsm4(ah[mt][0], ah[mt][1], ah[mt][2], ah[mt][3], st + off);
            }
#pragma unroll
            for (int q = 0; q < 4; q++) {
                int row = nrow0 + q * 16;
                uint32_t off = row * 128 + ((bch ^ (row & 7)) << 4);
                ldsm4(bh[q][0], bh[q][1], bh[q][2], bh[q][3], st + 16384 + off);
            }
#pragma unroll
            for (int mt = 0; mt < 2; mt++) {
#pragma unroll
                for (int nt = 0; nt < 8; nt++) {
                    int q = nt >> 1, o = (nt & 1) * 2;
                    mma16816(acc[mt][nt], ah[mt], bh[q][o], bh[q][o + 1]);
                }
            }
        }
    }

    // Epilogue: add bias, write fp32 directly
    const float* bptr = bias + bn * BN + wn * 64;
    size_t outbase = (size_t)(bm * BM + wm * 32) * 4096 + bn * BN + wn * 64;
    int gid = lane >> 2, tig = lane & 3;
#pragma unroll
    for (int nt = 0; nt < 8; nt++) {
        int c = nt * 8 + tig * 2;
        float b0 = bptr[c], b1 = bptr[c + 1];
#pragma unroll
        for (int mt = 0; mt < 2; mt++) {
            int r = mt * 16 + gid;
            float2 v0 = make_float2(acc[mt][nt][0] + b0, acc[mt][nt][1] + b1);
            float2 v1 = make_float2(acc[mt][nt][2] + b0, acc[mt][nt][3] + b1);
            *reinterpret_cast<float2*>(out + outbase + (size_t)r * 4096 + c) = v0;
            *reinterpret_cast<float2*>(out + outbase + (size_t)(r + 8) * 4096 + c) = v1;
        }
    }
}

// ---------------------------------------------------------------------------
extern "C" void kernel_launch(void* const* d_in, const int* in_sizes, int n_in,
                              void* d_out, int out_size) {
    const float* x  = (const float*)d_in[0];
    const float* W  = (const float*)d_in[1];
    const float* b  = (const float*)d_in[2];
    const float* Au = (const float*)d_in[3];
    const float* Bu = (const float*)d_in[4];
    const float* A0 = (const float*)d_in[5];
    const float* B0 = (const float*)d_in[6];
    float* out = (float*)d_out;

    int n4 = (MTOT * KTOT) / 4;
    split_x_kernel<<<(n4 + 255) / 256, 256>>>((const float4*)x, n4);
    build_w_kernel<<<dim3(KTOT / 128, NTOT / 32), 128>>>(W, Au, Bu, A0, B0);

    cudaFuncSetAttribute(gemm_kernel,
                         cudaFuncAttributeMaxDynamicSharedMemorySize,
                         NSTAGES * SSTAGE);
    gemm_kernel<<<dim3(NTOT / BN, MTOT / BM), 512, NSTAGES * SSTAGE>>>(b, out);
}